// round 2
// baseline (speedup 1.0000x reference)
#include <cuda_runtime.h>

// Shapes
#define NB   8
#define NTOK 8192      // N * I * J
#define XD   256
#define RD   256
#define UD   64
#define VD   64
#define HD   128

// Scratch (allocation-free: __device__ globals)
__device__ float g_t[NB * RD * HD];      // t[n,r,h]   : 262,144 floats
__device__ float g_v[NTOK * HD];         // v[tok,h]   : 1,048,576 floats

// ---------------------------------------------------------------------------
// Kernel A: t[n,r,h] = sum_u ( sum_v u[n,r,u,v] ) * w1[r,u,h]
// grid = (NB*RD) blocks, 128 threads. One block per (n, r).
// ---------------------------------------------------------------------------
__global__ void kA(const float* __restrict__ u, const float* __restrict__ w1) {
    const int n   = blockIdx.x >> 8;
    const int rr  = blockIdx.x & 255;
    const int tid = threadIdx.x;            // 0..127

    __shared__ float us[UD * VD];           // 4096 floats = 16KB
    __shared__ float s[UD];

    const float* ub = u + (size_t)(n * RD + rr) * (UD * VD);
    for (int i = tid; i < UD * VD; i += 128) us[i] = ub[i];
    __syncthreads();

    if (tid < UD) {
        float acc = 0.f;
        // rotated access -> conflict-free banks
        #pragma unroll 8
        for (int v = 0; v < VD; v++)
            acc += us[tid * VD + ((v + tid) & (VD - 1))];
        s[tid] = acc;
    }
    __syncthreads();

    float acc = 0.f;
    const float* w1b = w1 + (size_t)rr * UD * HD + tid;   // h = tid, coalesced
    #pragma unroll 8
    for (int uu = 0; uu < UD; uu++)
        acc += s[uu] * w1b[uu * HD];
    g_t[(n * RD + rr) * HD + tid] = acc;
}

// ---------------------------------------------------------------------------
// Kernel B: v[tok,h] = relu( sum_r r[tok,rr] * t[n,rr,h] )
// grid = NTOK/16 blocks, 128 threads (h = tid), 16 tokens per block.
// ---------------------------------------------------------------------------
__global__ void kB(const float* __restrict__ r) {
    const int b    = blockIdx.x;
    const int tid  = threadIdx.x;           // h
    const int tok0 = b * 16;
    const int n    = tok0 >> 10;            // 1024 tokens per n

    __shared__ float rs[16 * RD];           // 16KB
    const float* rb = r + (size_t)tok0 * RD;
    for (int i = tid; i < 16 * RD; i += 128) rs[i] = rb[i];
    __syncthreads();

    float acc[16];
    #pragma unroll
    for (int t = 0; t < 16; t++) acc[t] = 0.f;

    const float* tb = g_t + (size_t)n * RD * HD + tid;
    for (int rr = 0; rr < RD; rr += 4) {
        const float w0 = tb[(rr + 0) * HD];
        const float w1v = tb[(rr + 1) * HD];
        const float w2v = tb[(rr + 2) * HD];
        const float w3v = tb[(rr + 3) * HD];
        #pragma unroll
        for (int t = 0; t < 16; t++) {
            float4 rv = *reinterpret_cast<const float4*>(&rs[t * RD + rr]);
            acc[t] += rv.x * w0 + rv.y * w1v + rv.z * w2v + rv.w * w3v;
        }
    }
    #pragma unroll
    for (int t = 0; t < 16; t++)
        g_v[(size_t)(tok0 + t) * HD + tid] = fmaxf(acc[t], 0.f);
}

// ---------------------------------------------------------------------------
// Kernel C (dominant): out[tok,vv] = sum_h v[tok,h] * ( sum_x x[tok,x] * w2[x,vv,h] )
// grid = NTOK/32 blocks, 256 threads. 32-token tile.
// Thread layout: h = tid & 127, half = tid >> 7 (vv = half*32 + vvi).
// Per vv: accumulate m[t,h] over x (LDS.128 broadcast of x tile, coalesced w2
// loads across h), then p = m*v, warp shuffle-reduce over 32 h, 4 warps
// combine via shared atomics.
// ---------------------------------------------------------------------------
__global__ void kC(const float* __restrict__ x, const float* __restrict__ w2,
                   float* __restrict__ out) {
    extern __shared__ float sm[];
    float* xs = sm;                          // 32 * 256
    float* vs = xs + 32 * XD;                // 32 * 128
    float* os = vs + 32 * HD;                // 32 * 64

    const int tid  = threadIdx.x;            // 0..255
    const int b    = blockIdx.x;
    const int tok0 = b * 32;

    const float* xb = x + (size_t)tok0 * XD;
    for (int i = tid; i < 32 * XD; i += 256) xs[i] = xb[i];
    const float* vb = g_v + (size_t)tok0 * HD;
    for (int i = tid; i < 32 * HD; i += 256) vs[i] = vb[i];
    for (int i = tid; i < 32 * VD; i += 256) os[i] = 0.f;
    __syncthreads();

    const int h    = tid & 127;
    const int half = tid >> 7;
    const int lane = tid & 31;

    for (int vvi = 0; vvi < 32; vvi++) {
        const int vv = half * 32 + vvi;
        float acc[32];
        #pragma unroll
        for (int t = 0; t < 32; t++) acc[t] = 0.f;

        const float* w2b = w2 + (size_t)vv * HD + h;   // + xd * VD*HD
        for (int xd = 0; xd < XD; xd += 4) {
            const float wa = w2b[(size_t)(xd + 0) * (VD * HD)];
            const float wb = w2b[(size_t)(xd + 1) * (VD * HD)];
            const float wc = w2b[(size_t)(xd + 2) * (VD * HD)];
            const float wd = w2b[(size_t)(xd + 3) * (VD * HD)];
            #pragma unroll
            for (int t = 0; t < 32; t++) {
                float4 xv = *reinterpret_cast<const float4*>(&xs[t * XD + xd]);
                acc[t] += xv.x * wa + xv.y * wb + xv.z * wc + xv.w * wd;
            }
        }

        // p[t] = m[t,h] * v[t,h]; reduce over h (warp covers 32 consecutive h,
        // 4 warps per half combine via smem atomics)
        #pragma unroll
        for (int t = 0; t < 32; t++) {
            float p = acc[t] * vs[t * HD + h];
            p += __shfl_xor_sync(0xffffffffu, p, 16);
            p += __shfl_xor_sync(0xffffffffu, p, 8);
            p += __shfl_xor_sync(0xffffffffu, p, 4);
            p += __shfl_xor_sync(0xffffffffu, p, 2);
            p += __shfl_xor_sync(0xffffffffu, p, 1);
            if (lane == 0) atomicAdd(&os[t * VD + vv], p);
        }
    }
    __syncthreads();

    float* ob = out + (size_t)tok0 * VD;
    for (int i = tid; i < 32 * VD; i += 256) ob[i] = os[i];
}

// ---------------------------------------------------------------------------
extern "C" void kernel_launch(void* const* d_in, const int* in_sizes, int n_in,
                              void* d_out, int out_size) {
    const float* x  = (const float*)d_in[0];
    const float* r  = (const float*)d_in[1];
    const float* u  = (const float*)d_in[2];
    const float* w1 = (const float*)d_in[3];
    const float* w2 = (const float*)d_in[4];
    float* out = (float*)d_out;

    // 56KB dynamic smem for kC (idempotent, capture-safe, called every time)
    const int kc_smem = (32 * XD + 32 * HD + 32 * VD) * (int)sizeof(float);
    cudaFuncSetAttribute(kC, cudaFuncAttributeMaxDynamicSharedMemorySize, kc_smem);

    kA<<<NB * RD, 128>>>(u, w1);
    kB<<<NTOK / 16, 128>>>(r);
    kC<<<NTOK / 32, 256, kc_smem>>>(x, w2, out);
}

// round 3
// speedup vs baseline: 5.6181x; 5.6181x over previous
#include <cuda_runtime.h>
#include <cstdint>

// Shapes
#define NB   8
#define NTOK 8192      // N * I * J
#define XD   256
#define RD   256
#define UD   64
#define VD   64
#define HD   128

// Scratch (allocation-free: __device__ globals)
__device__ float g_t[NB * RD * HD];        // t[n,r,h]
__device__ float g_v[NTOK * HD];           // v[tok,h]
__device__ float g_w2t[XD * VD * HD];      // rna-rounded-to-tf32 copy of w2 (8MB)
__device__ float g_part[2][NTOK * VD];     // K-split partial sums (4MB)

// ---------------------------------------------------------------------------
// Kernel W: g_w2t = round_to_nearest_tf32(w2). Unbiased rounding once, so the
// tensor-core path has no truncation bias.
// ---------------------------------------------------------------------------
__global__ void kW(const float* __restrict__ w2) {
    int i = (blockIdx.x * 256 + threadIdx.x) * 4;
    float4 v = *reinterpret_cast<const float4*>(w2 + i);
    uint32_t r0, r1, r2, r3;
    asm("cvt.rna.tf32.f32 %0, %1;" : "=r"(r0) : "f"(v.x));
    asm("cvt.rna.tf32.f32 %0, %1;" : "=r"(r1) : "f"(v.y));
    asm("cvt.rna.tf32.f32 %0, %1;" : "=r"(r2) : "f"(v.z));
    asm("cvt.rna.tf32.f32 %0, %1;" : "=r"(r3) : "f"(v.w));
    float4 o;
    o.x = __uint_as_float(r0); o.y = __uint_as_float(r1);
    o.z = __uint_as_float(r2); o.w = __uint_as_float(r3);
    *reinterpret_cast<float4*>(g_w2t + i) = o;
}

// ---------------------------------------------------------------------------
// Kernel A: t[n,r,h] = sum_u ( sum_v u[n,r,u,v] ) * w1[r,u,h]
// ---------------------------------------------------------------------------
__global__ void kA(const float* __restrict__ u, const float* __restrict__ w1) {
    const int n   = blockIdx.x >> 8;
    const int rr  = blockIdx.x & 255;
    const int tid = threadIdx.x;            // 0..127

    __shared__ float us[UD * VD];
    __shared__ float s[UD];

    const float* ub = u + (size_t)(n * RD + rr) * (UD * VD);
    for (int i = tid; i < UD * VD; i += 128) us[i] = ub[i];
    __syncthreads();

    if (tid < UD) {
        float acc = 0.f;
        #pragma unroll 8
        for (int v = 0; v < VD; v++)
            acc += us[tid * VD + ((v + tid) & (VD - 1))];
        s[tid] = acc;
    }
    __syncthreads();

    float acc = 0.f;
    const float* w1b = w1 + (size_t)rr * UD * HD + tid;   // h = tid, coalesced
    #pragma unroll 8
    for (int uu = 0; uu < UD; uu++)
        acc += s[uu] * w1b[uu * HD];
    g_t[(n * RD + rr) * HD + tid] = acc;
}

// ---------------------------------------------------------------------------
// Kernel B: v[tok,h] = relu( sum_r r[tok,rr] * t[n,rr,h] )
// ---------------------------------------------------------------------------
__global__ void kB(const float* __restrict__ r) {
    const int b    = blockIdx.x;
    const int tid  = threadIdx.x;           // h
    const int tok0 = b * 16;
    const int n    = tok0 >> 10;

    __shared__ float rs[16 * RD];
    const float* rb = r + (size_t)tok0 * RD;
    for (int i = tid; i < 16 * RD; i += 128) rs[i] = rb[i];
    __syncthreads();

    float acc[16];
    #pragma unroll
    for (int t = 0; t < 16; t++) acc[t] = 0.f;

    const float* tb = g_t + (size_t)n * RD * HD + tid;
    for (int rr = 0; rr < RD; rr += 4) {
        const float w0  = tb[(rr + 0) * HD];
        const float w1v = tb[(rr + 1) * HD];
        const float w2v = tb[(rr + 2) * HD];
        const float w3v = tb[(rr + 3) * HD];
        #pragma unroll
        for (int t = 0; t < 16; t++) {
            float4 rv = *reinterpret_cast<const float4*>(&rs[t * RD + rr]);
            acc[t] += rv.x * w0 + rv.y * w1v + rv.z * w2v + rv.w * w3v;
        }
    }
    #pragma unroll
    for (int t = 0; t < 16; t++)
        g_v[(size_t)(tok0 + t) * HD + tid] = fmaxf(acc[t], 0.f);
}

// ---------------------------------------------------------------------------
// Kernel C (dominant, tensor cores):
//   out[t,vv] = sum_{x,h} (x[t,x]*v[t,h]) * w2[x,vv,h]
// GEMM M=8192, N=64, K=32768 via mma.sync.m16n8k8.tf32.
// A fragments generated in registers per x0 (rank-1: x[t,x0] * v[t,h]);
// v fragments hoisted into registers (x0-invariant).
// B tile per x0 = w2[x0] (native [64,128] row-major = B^T), cp.async
// double-buffered. Grid = 64 token-tiles (128 tok) x 2 K-splits over x.
// ---------------------------------------------------------------------------
#define XS 132   // padded row stride (floats) for x tile
#define BS 132   // padded row stride (floats) for w2 tile

__global__ __launch_bounds__(256, 1) void kC(const float* __restrict__ x) {
    extern __shared__ float sm[];
    float* xs  = sm;                   // 128 x 132
    float* b0s = xs + 128 * XS;        // 64 x 132
    float* b1s = b0s + 64 * BS;        // 64 x 132
    float* vs  = b1s + 64 * BS;        // 128 x 128

    const int tid   = threadIdx.x;
    const int split = blockIdx.x >> 6;        // 0/1 : x-range half
    const int tile  = blockIdx.x & 63;        // token tile
    const int tok0  = tile * 128;
    const int xbase = split * 128;

    // Stage x half-tile [128 tok x 128 x] and v tile [128 tok x 128 h]
    {
        const float4* xg = reinterpret_cast<const float4*>(x + (size_t)tok0 * XD + xbase);
        #pragma unroll
        for (int j = 0; j < 16; j++) {
            int idx = tid + j * 256;          // 0..4095 float4
            int row = idx >> 5, c4 = idx & 31;
            float4 val = xg[row * (XD / 4) + c4];
            *reinterpret_cast<float4*>(&xs[row * XS + c4 * 4]) = val;
        }
        const float4* vg = reinterpret_cast<const float4*>(g_v + (size_t)tok0 * HD);
        #pragma unroll
        for (int j = 0; j < 16; j++) {
            int idx = tid + j * 256;
            reinterpret_cast<float4*>(vs)[idx] = vg[idx];
        }
    }
    __syncthreads();

    const int lane = tid & 31, warp = tid >> 5;
    const int g  = lane >> 2, kl = lane & 3;
    const int ta = warp * 16 + g;             // A rows handled by this thread
    const int tb2 = ta + 8;

    // Hoist v fragments (x0-invariant): 64 registers
    float va0[16], va4[16], vb0[16], vb4[16];
    #pragma unroll
    for (int hc = 0; hc < 16; hc++) {
        int h = hc * 8;
        va0[hc] = vs[ta  * HD + h + kl];
        va4[hc] = vs[ta  * HD + h + kl + 4];
        vb0[hc] = vs[tb2 * HD + h + kl];
        vb4[hc] = vs[tb2 * HD + h + kl + 4];
    }

    float c[8][4];
    #pragma unroll
    for (int nt = 0; nt < 8; nt++) {
        c[nt][0] = 0.f; c[nt][1] = 0.f; c[nt][2] = 0.f; c[nt][3] = 0.f;
    }

    // cp.async loader for w2[x0] tile: 8192 floats -> padded 64x132
    auto cpB = [&](int x0, float* dst) {
        const float* src = g_w2t + (size_t)(xbase + x0) * (VD * HD);
        #pragma unroll
        for (int j = 0; j < 8; j++) {
            int idx = tid + j * 256;          // 0..2047 float4
            int row = idx >> 5, c4 = idx & 31;
            uint32_t daddr = (uint32_t)__cvta_generic_to_shared(&dst[row * BS + c4 * 4]);
            asm volatile("cp.async.cg.shared.global [%0], [%1], 16;\n"
                         :: "r"(daddr), "l"(src + idx * 4) : "memory");
        }
    };

    cpB(0, b0s);
    asm volatile("cp.async.commit_group;\n" ::: "memory");

    for (int x0 = 0; x0 < 128; x0++) {
        if (x0 + 1 < 128) cpB(x0 + 1, ((x0 + 1) & 1) ? b1s : b0s);
        asm volatile("cp.async.commit_group;\n" ::: "memory");
        asm volatile("cp.async.wait_group 1;\n" ::: "memory");
        __syncthreads();

        const uint32_t* Bu = reinterpret_cast<const uint32_t*>((x0 & 1) ? b1s : b0s);
        const float xa = xs[ta  * XS + x0];
        const float xb = xs[tb2 * XS + x0];

        #pragma unroll
        for (int hc = 0; hc < 16; hc++) {
            // A fragment: A[t, kk] = x[t,x0] * v[t, hc*8+kk], rna-rounded (unbiased)
            float f0 = xa * va0[hc];
            float f1 = xb * vb0[hc];
            float f2 = xa * va4[hc];
            float f3 = xb * vb4[hc];
            uint32_t A0, A1, A2, A3;
            asm("cvt.rna.tf32.f32 %0, %1;" : "=r"(A0) : "f"(f0));
            asm("cvt.rna.tf32.f32 %0, %1;" : "=r"(A1) : "f"(f1));
            asm("cvt.rna.tf32.f32 %0, %1;" : "=r"(A2) : "f"(f2));
            asm("cvt.rna.tf32.f32 %0, %1;" : "=r"(A3) : "f"(f3));

            #pragma unroll
            for (int nt = 0; nt < 8; nt++) {
                uint32_t B0 = Bu[(nt * 8 + g) * BS + hc * 8 + kl];
                uint32_t B1 = Bu[(nt * 8 + g) * BS + hc * 8 + kl + 4];
                asm volatile(
                    "mma.sync.aligned.m16n8k8.row.col.f32.tf32.tf32.f32 "
                    "{%0,%1,%2,%3}, {%4,%5,%6,%7}, {%8,%9}, {%0,%1,%2,%3};\n"
                    : "+f"(c[nt][0]), "+f"(c[nt][1]), "+f"(c[nt][2]), "+f"(c[nt][3])
                    : "r"(A0), "r"(A1), "r"(A2), "r"(A3), "r"(B0), "r"(B1));
            }
        }
        __syncthreads();   // protect the buffer refilled next iteration
    }

    // Epilogue: write partials (row ta cols nt*8+2*kl(+1); row ta+8 same cols)
    float* pp = g_part[split];
    #pragma unroll
    for (int nt = 0; nt < 8; nt++) {
        int col = nt * 8 + kl * 2;
        *reinterpret_cast<float2*>(&pp[(size_t)(tok0 + ta)  * VD + col]) =
            make_float2(c[nt][0], c[nt][1]);
        *reinterpret_cast<float2*>(&pp[(size_t)(tok0 + tb2) * VD + col]) =
            make_float2(c[nt][2], c[nt][3]);
    }
}

// ---------------------------------------------------------------------------
// Kernel D: out = part0 + part1 (deterministic K-split combine)
// ---------------------------------------------------------------------------
__global__ void kD(float* __restrict__ out) {
    int i = blockIdx.x * 256 + threadIdx.x;   // float4 index
    float4 a = reinterpret_cast<const float4*>(g_part[0])[i];
    float4 b = reinterpret_cast<const float4*>(g_part[1])[i];
    float4 o;
    o.x = a.x + b.x; o.y = a.y + b.y; o.z = a.z + b.z; o.w = a.w + b.w;
    reinterpret_cast<float4*>(out)[i] = o;
}

// ---------------------------------------------------------------------------
extern "C" void kernel_launch(void* const* d_in, const int* in_sizes, int n_in,
                              void* d_out, int out_size) {
    const float* x  = (const float*)d_in[0];
    const float* r  = (const float*)d_in[1];
    const float* u  = (const float*)d_in[2];
    const float* w1 = (const float*)d_in[3];
    const float* w2 = (const float*)d_in[4];
    float* out = (float*)d_out;

    const int kc_smem = (128 * XS + 2 * 64 * BS + 128 * HD) * (int)sizeof(float);
    cudaFuncSetAttribute(kC, cudaFuncAttributeMaxDynamicSharedMemorySize, kc_smem);

    kW<<<(XD * VD * HD) / 1024, 256>>>(w2);
    kA<<<NB * RD, 128>>>(u, w1);
    kB<<<NTOK / 16, 128>>>(r);
    kC<<<128, 256, kc_smem>>>(x);
    kD<<<(NTOK * VD) / 1024, 256>>>(out);
}